// round 14
// baseline (speedup 1.0000x reference)
#include <cuda_runtime.h>
#include <cuda_fp16.h>
#include <cstdint>

#define Hd   64
#define Wd   64
#define HW   4096
#define Bd   4
#define Cd   256
#define COd  256
#define KDIM 2304
#define NTOT 16384
#define NGRP 16
#define CPG  16

// GEMM tiling: CTA tile 128m x 64n x 32k, warp tile 32x32, 8 warps, 3 CTA/SM
#define BM 128
#define BN 64
#define BK 32
#define NSTG (KDIM / BK)       // 72 stages
#define A_ROW_B  80
#define B_ROW_B  80
#define A_OFF    0
#define B_OFF    10240
#define STAGE_B  15360
#define NBUF     4
#define SMEM_TOTAL (NBUF * STAGE_B)   // 61440

// input transposed to NHWC fp16: [b][hw][c]
__device__ __align__(256) __half g_inT[(size_t)Bd * HW * Cd];
// im2col columns fp16, layout [n][k'] with k' = kk*256 + c
__device__ __align__(256) __half g_cols[(size_t)NTOT * KDIM];
// weights fp16, [o][k'] with k' = kk*256 + c
__device__ __align__(256) __half g_w[COd * KDIM];
// groupnorm partials: [b*16+g][128] (64 n-tiles x 2 wn-warps)
__device__ float2 g_part2[64 * 128];
// finalized per (b,g): (mu, rsqrt(var+eps))
__device__ float2 g_mufin[64];

// ---------------------------------------------------------------------------
__device__ __forceinline__ uint32_t smem_u32(const void* p) {
    uint32_t a;
    asm("{ .reg .u64 t; cvta.to.shared.u64 t, %1; cvt.u32.u64 %0, t; }" : "=r"(a) : "l"(p));
    return a;
}
#define CP_ASYNC(dst, src) \
    asm volatile("cp.async.cg.shared.global [%0], [%1], 16;" :: "r"(dst), "l"(src))
#define CP_COMMIT() asm volatile("cp.async.commit_group;")
#define CP_WAIT(n)  asm volatile("cp.async.wait_group %0;" :: "n"(n))

#define LDMATRIX_X4(r0, r1, r2, r3, a) \
    asm volatile("ldmatrix.sync.aligned.m8n8.x4.shared.b16 {%0,%1,%2,%3}, [%4];" \
        : "=r"(r0), "=r"(r1), "=r"(r2), "=r"(r3) : "r"(a))

#define MMA_F16(d, a, b0v, b1v) \
    asm volatile("mma.sync.aligned.m16n8k16.row.col.f32.f16.f16.f32 " \
        "{%0,%1,%2,%3}, {%4,%5,%6,%7}, {%8,%9}, {%0,%1,%2,%3};" \
        : "+f"((d)[0]), "+f"((d)[1]), "+f"((d)[2]), "+f"((d)[3]) \
        : "r"((a)[0]), "r"((a)[1]), "r"((a)[2]), "r"((a)[3]), "r"(b0v), "r"(b1v))

// ---------------------------------------------------------------------------
// Kernel 0a: weights fp16 with K permutation k' = kk*256 + c
// ---------------------------------------------------------------------------
__global__ __launch_bounds__(256) void wprep_kernel(const float* __restrict__ w) {
    int i = blockIdx.x * 256 + threadIdx.x;
    const int o  = i / KDIM;
    const int r  = i - o * KDIM;
    const int kk = r >> 8;
    const int c  = r & 255;
    g_w[i] = __float2half_rn(w[(o * Cd + c) * 9 + kk]);
}

// ---------------------------------------------------------------------------
// Kernel 0b: transpose input NCHW fp32 -> NHWC fp16
// ---------------------------------------------------------------------------
__global__ __launch_bounds__(256) void tprep_kernel(const float* __restrict__ in) {
    __shared__ float tile[32][33];
    const int hw0 = blockIdx.x * 32;
    const int c0  = blockIdx.y * 32;
    const int b   = blockIdx.z;
    const int tx  = threadIdx.x, ty = threadIdx.y;

#pragma unroll
    for (int j = 0; j < 4; ++j) {
        const int c = c0 + ty + j * 8;
        tile[ty + j * 8][tx] = in[((size_t)(b * Cd + c)) * HW + hw0 + tx];
    }
    __syncthreads();
#pragma unroll
    for (int j = 0; j < 4; ++j) {
        const int hw = hw0 + ty + j * 8;
        g_inT[((size_t)(b * HW + hw)) * Cd + c0 + tx] = __float2half_rn(tile[tx][ty + j * 8]);
    }
}

// ---------------------------------------------------------------------------
// Kernel 1: deformable bilinear sampling, NHWC (known good).
// ---------------------------------------------------------------------------
__global__ __launch_bounds__(256) void sample_kernel(
    const float* __restrict__ off, const float* __restrict__ mask)
{
    const int warp  = blockIdx.x * 8 + (threadIdx.x >> 5);
    const int lane  = threadIdx.x & 31;
    const int c0    = lane * 8;
    const int site0 = warp * 8;

#pragma unroll
    for (int it = 0; it < 8; ++it) {
        const int site = site0 + it;
        const int n  = site & (NTOT - 1);
        const int kk = site >> 14;
        const int b  = n >> 12;
        const int hw = n & 4095;
        const int h  = hw >> 6;
        const int w  = hw & 63;

        const float dy = off[((b * 18 + 2 * kk)     << 12) + hw];
        const float dx = off[((b * 18 + 2 * kk + 1) << 12) + hw];
        const float m  = mask[((b * 9 + kk)         << 12) + hw];

        const float y = (float)h + (float)(kk / 3 - 1) + dy;
        const float x = (float)w + (float)(kk % 3 - 1) + dx;
        const float y0f = floorf(y), x0f = floorf(x);
        const int   y0 = (int)y0f,  x0 = (int)x0f;
        const float wy1 = y - y0f, wx1 = x - x0f;
        const float wy0 = 1.0f - wy1, wx0 = 1.0f - wx1;

        const bool vy0 = (y0 >= 0) && (y0 < Hd);
        const bool vy1 = (y0 + 1 >= 0) && (y0 + 1 < Hd);
        const bool vx0 = (x0 >= 0) && (x0 < Wd);
        const bool vx1 = (x0 + 1 >= 0) && (x0 + 1 < Wd);

        const float w00 = (vy0 && vx0) ? wy0 * wx0 * m : 0.0f;
        const float w01 = (vy0 && vx1) ? wy0 * wx1 * m : 0.0f;
        const float w10 = (vy1 && vx0) ? wy1 * wx0 * m : 0.0f;
        const float w11 = (vy1 && vx1) ? wy1 * wx1 * m : 0.0f;

        const int i00 = (vy0 && vx0) ? (y0       * Wd + x0    ) : 0;
        const int i01 = (vy0 && vx1) ? (y0       * Wd + x0 + 1) : 0;
        const int i10 = (vy1 && vx0) ? ((y0 + 1) * Wd + x0    ) : 0;
        const int i11 = (vy1 && vx1) ? ((y0 + 1) * Wd + x0 + 1) : 0;

        const __half* base = g_inT + ((size_t)b * HW) * Cd + c0;
        union { uint4 u; __half2 h[4]; } u00, u01, u10, u11, res;
        u00.u = *(const uint4*)(base + (size_t)i00 * Cd);
        u01.u = *(const uint4*)(base + (size_t)i01 * Cd);
        u10.u = *(const uint4*)(base + (size_t)i10 * Cd);
        u11.u = *(const uint4*)(base + (size_t)i11 * Cd);

#pragma unroll
        for (int j = 0; j < 4; ++j) {
            const float2 f00 = __half22float2(u00.h[j]);
            const float2 f01 = __half22float2(u01.h[j]);
            const float2 f10 = __half22float2(u10.h[j]);
            const float2 f11 = __half22float2(u11.h[j]);
            const float rx = w00 * f00.x + w01 * f01.x + w10 * f10.x + w11 * f11.x;
            const float ry = w00 * f00.y + w01 * f01.y + w10 * f10.y + w11 * f11.y;
            res.h[j] = __floats2half2_rn(rx, ry);
        }
        *(uint4*)(g_cols + (size_t)n * KDIM + kk * 256 + c0) = res.u;
    }
}

// ---------------------------------------------------------------------------
// Stage loader: cp.async one stage (A 512 + B 256 chunks), 3 per thread
// ---------------------------------------------------------------------------
__device__ __forceinline__ void load_stage(uint32_t sbuf, int s, int m0, int n0, int tid)
{
    const int k0 = s * BK;
#pragma unroll
    for (int j = 0; j < 3; ++j) {
        const int c = tid + j * 256;
        if (c < 512) {                // A: 128 rows x 4 chunks
            const int row = c >> 2, seg = c & 3;
            const __half* src = g_w + (m0 + row) * KDIM + k0 + seg * 8;
            CP_ASYNC(sbuf + A_OFF + row * A_ROW_B + seg * 16, src);
        } else {                      // B: 64 n-rows x 4 chunks
            const int cc  = c - 512;
            const int row = cc >> 2, seg = cc & 3;
            const __half* src = g_cols + (size_t)(n0 + row) * KDIM + k0 + seg * 8;
            CP_ASYNC(sbuf + B_OFF + row * B_ROW_B + seg * 16, src);
        }
    }
    CP_COMMIT();
}

// ---------------------------------------------------------------------------
// Kernel 2: fp16 GEMM via mma.sync + fused GN partial stats.
// grid (2 m-tiles, 256 n-tiles), 256 threads, warp tile 32x32, 3 CTA/SM.
// ---------------------------------------------------------------------------
__global__ __launch_bounds__(256, 3) void gemm_mma(
    const float* __restrict__ bias, float* __restrict__ out)
{
    extern __shared__ char smem[];
    const uint32_t sb = smem_u32(smem);
    const int tid = threadIdx.x;
    const int wid = tid >> 5;
    const int lid = tid & 31;
    const int wm  = wid >> 1;        // 0..3 -> 32-row warp tile
    const int wn  = wid & 1;         // 0..1 -> 32-col warp tile
    const int m0  = blockIdx.x * BM;
    const int n0  = blockIdx.y * BN;

    float acc[2][4][4];
#pragma unroll
    for (int i = 0; i < 2; ++i)
#pragma unroll
        for (int j = 0; j < 4; ++j)
#pragma unroll
            for (int r = 0; r < 4; ++r) acc[i][j][r] = 0.0f;

    load_stage(sb, 0, m0, n0, tid);
    load_stage(sb + STAGE_B, 1, m0, n0, tid);
    load_stage(sb + 2 * STAGE_B, 2, m0, n0, tid);

    const uint32_t a_lane = (uint32_t)((lid & 15) * A_ROW_B + (lid >> 4) * 16);
    const uint32_t b_lane = (uint32_t)((((lid >> 4) << 3) + (lid & 7)) * B_ROW_B
                                       + ((lid >> 3) & 1) * 16);

    for (int s = 0; s < NSTG; ++s) {
        if (s + 3 < NSTG) { CP_WAIT(2); } else { CP_WAIT(0); }
        __syncthreads();
        if (s + 3 < NSTG)
            load_stage(sb + (uint32_t)((s + 3) & 3) * STAGE_B, s + 3, m0, n0, tid);

        const uint32_t sbuf = sb + (uint32_t)(s & 3) * STAGE_B;

#pragma unroll
        for (int kkp = 0; kkp < 2; ++kkp) {
            uint32_t af[2][4];
#pragma unroll
            for (int i = 0; i < 2; ++i) {
                const uint32_t addr = sbuf + A_OFF + (uint32_t)((wm * 32 + i * 16) * A_ROW_B)
                                    + (uint32_t)(kkp * 32) + a_lane;
                LDMATRIX_X4(af[i][0], af[i][1], af[i][2], af[i][3], addr);
            }
            uint32_t bf[2][4];
#pragma unroll
            for (int j2 = 0; j2 < 2; ++j2) {
                const uint32_t addr = sbuf + B_OFF + (uint32_t)((wn * 32 + j2 * 16) * B_ROW_B)
                                    + (uint32_t)(kkp * 32) + b_lane;
                LDMATRIX_X4(bf[j2][0], bf[j2][1], bf[j2][2], bf[j2][3], addr);
            }
#pragma unroll
            for (int i = 0; i < 2; ++i)
#pragma unroll
                for (int j = 0; j < 4; ++j)
                    MMA_F16(acc[i][j], af[i], bf[j >> 1][(j & 1) * 2], bf[j >> 1][(j & 1) * 2 + 1]);
        }
    }

    // epilogue: write out + per-group warp-reduced partial stats.
    // acc[i] block = 16 channels (group m0/16 + wm*2 + i) x 32 n.
    const int b   = n0 >> 12;
    const int hwb = n0 & 4095;
    const int slot = ((blockIdx.y & 63) << 1) + wn;   // 0..127
#pragma unroll
    for (int i = 0; i < 2; ++i) {
        const int o_lo = m0 + wm * 32 + i * 16 + (lid >> 2);
        const float bi0 = bias[o_lo];
        const float bi1 = bias[o_lo + 8];
        float s = 0.0f, q = 0.0f;
#pragma unroll
        for (int j = 0; j < 4; ++j) {
            const int nc = hwb + wn * 32 + j * 8 + (lid & 3) * 2;
            float v0x = acc[i][j][0] + bi0, v0y = acc[i][j][1] + bi0;
            float v1x = acc[i][j][2] + bi1, v1y = acc[i][j][3] + bi1;
            s += v0x + v0y + v1x + v1y;
            q += v0x * v0x + v0y * v0y + v1x * v1x + v1y * v1y;
            *(float2*)(out + (((size_t)(b * COd + o_lo))     << 12) + nc) = make_float2(v0x, v0y);
            *(float2*)(out + (((size_t)(b * COd + o_lo + 8)) << 12) + nc) = make_float2(v1x, v1y);
        }
#pragma unroll
        for (int d = 16; d > 0; d >>= 1) {
            s += __shfl_xor_sync(0xFFFFFFFFu, s, d);
            q += __shfl_xor_sync(0xFFFFFFFFu, q, d);
        }
        if (lid == 0) {
            const int g = (m0 >> 4) + wm * 2 + i;      // 0..15
            g_part2[(b * 16 + g) * 128 + slot] = make_float2(s, q);
        }
    }
}

// ---------------------------------------------------------------------------
// Kernel 3: finalize stats — 64 blocks x 128 thr, one (b,g) per block.
// ---------------------------------------------------------------------------
__global__ __launch_bounds__(128) void finalize_kernel()
{
    __shared__ float sh_s[128], sh_q[128];
    const int bg = blockIdx.x;
    float2 p = g_part2[bg * 128 + threadIdx.x];
    sh_s[threadIdx.x] = p.x;
    sh_q[threadIdx.x] = p.y;
    __syncthreads();
    for (int st = 64; st > 0; st >>= 1) {
        if (threadIdx.x < st) {
            sh_s[threadIdx.x] += sh_s[threadIdx.x + st];
            sh_q[threadIdx.x] += sh_q[threadIdx.x + st];
        }
        __syncthreads();
    }
    if (threadIdx.x == 0) {
        const float cnt = 65536.0f;
        const float mu  = sh_s[0] / cnt;
        const float var = sh_q[0] / cnt - mu * mu;
        g_mufin[bg] = make_float2(mu, rsqrtf(var + 1e-5f));
    }
}

// ---------------------------------------------------------------------------
// Kernel 4: normalize in place (reads finalized stats)
// ---------------------------------------------------------------------------
__global__ __launch_bounds__(256) void norm_kernel(
    float* __restrict__ out, const float* __restrict__ gamma,
    const float* __restrict__ beta)
{
    const int fi0 = blockIdx.x << 10;     // 1024 floats per block
    const int o   = (fi0 >> 12) & 255;
    const int b   = fi0 >> 20;
    const int bg  = b * 16 + (o >> 4);

    const float2 mf = g_mufin[bg];
    const float ga  = gamma[o] * mf.y;
    const float be  = beta[o] - mf.x * ga;

    const int idx = (fi0 >> 2) + threadIdx.x;
    float4 v = ((const float4*)out)[idx];
    v.x = v.x * ga + be; v.y = v.y * ga + be;
    v.z = v.z * ga + be; v.w = v.w * ga + be;
    ((float4*)out)[idx] = v;
}

// ---------------------------------------------------------------------------
extern "C" void kernel_launch(void* const* d_in, const int* in_sizes, int n_in,
                              void* d_out, int out_size)
{
    const float* input  = (const float*)d_in[0];
    const float* offset = (const float*)d_in[1];
    const float* mask   = (const float*)d_in[2];
    const float* weight = (const float*)d_in[3];
    const float* bias   = (const float*)d_in[4];
    const float* gamma  = (const float*)d_in[5];
    const float* beta   = (const float*)d_in[6];
    float* out = (float*)d_out;

    cudaFuncSetAttribute(gemm_mma, cudaFuncAttributeMaxDynamicSharedMemorySize, SMEM_TOTAL);

    wprep_kernel<<<COd * KDIM / 256, 256>>>(weight);

    dim3 gt(HW / 32, Cd / 32, Bd);
    tprep_kernel<<<gt, dim3(32, 8)>>>(input);

    sample_kernel<<<2304, 256>>>(offset, mask);

    dim3 gg(COd / BM, NTOT / BN);
    gemm_mma<<<gg, 256, SMEM_TOTAL>>>(bias, out);

    finalize_kernel<<<64, 128>>>();

    norm_kernel<<<Bd * COd * HW / 1024, 256>>>(out, gamma, beta);
}

// round 15
// speedup vs baseline: 1.2002x; 1.2002x over previous
#include <cuda_runtime.h>
#include <cuda_fp16.h>
#include <cstdint>

#define Hd   64
#define Wd   64
#define HW   4096
#define Bd   4
#define Cd   256
#define COd  256
#define KDIM 2304
#define NTOT 16384
#define NGRP 16
#define CPG  16

// GEMM tiling: CTA tile 128m x 128n x 64k, warp tile 64x32, 8 warps, 2 CTA/SM
#define BM 128
#define BN 128
#define BK 64
#define NSTG (KDIM / BK)       // 36 stages
#define A_ROW_B  144           // 64 fp16 = 128B data + 16B pad
#define B_ROW_B  144
#define A_OFF    0
#define B_OFF    18432
#define STAGE_B  36864
#define NBUF     2
#define SMEM_TOTAL (NBUF * STAGE_B)   // 73728

// input transposed to NHWC fp16: [b][hw][c]
__device__ __align__(256) __half g_inT[(size_t)Bd * HW * Cd];
// im2col columns fp16, layout [n][k'] with k' = kk*256 + c
__device__ __align__(256) __half g_cols[(size_t)NTOT * KDIM];
// weights fp16, [o][k'] with k' = kk*256 + c
__device__ __align__(256) __half g_w[COd * KDIM];
// groupnorm partials: [b*16+g][128] (32 n-tiles x 4 wn-warps)
__device__ float2 g_part2[64 * 128];
// finalized per (b,g): (mu, rsqrt(var+eps))
__device__ float2 g_mufin[64];

// ---------------------------------------------------------------------------
__device__ __forceinline__ uint32_t smem_u32(const void* p) {
    uint32_t a;
    asm("{ .reg .u64 t; cvta.to.shared.u64 t, %1; cvt.u32.u64 %0, t; }" : "=r"(a) : "l"(p));
    return a;
}
#define CP_ASYNC(dst, src) \
    asm volatile("cp.async.cg.shared.global [%0], [%1], 16;" :: "r"(dst), "l"(src))
#define CP_COMMIT() asm volatile("cp.async.commit_group;")
#define CP_WAIT(n)  asm volatile("cp.async.wait_group %0;" :: "n"(n))

#define LDMATRIX_X4(r0, r1, r2, r3, a) \
    asm volatile("ldmatrix.sync.aligned.m8n8.x4.shared.b16 {%0,%1,%2,%3}, [%4];" \
        : "=r"(r0), "=r"(r1), "=r"(r2), "=r"(r3) : "r"(a))

#define MMA_F16(d, a, b0v, b1v) \
    asm volatile("mma.sync.aligned.m16n8k16.row.col.f32.f16.f16.f32 " \
        "{%0,%1,%2,%3}, {%4,%5,%6,%7}, {%8,%9}, {%0,%1,%2,%3};" \
        : "+f"((d)[0]), "+f"((d)[1]), "+f"((d)[2]), "+f"((d)[3]) \
        : "r"((a)[0]), "r"((a)[1]), "r"((a)[2]), "r"((a)[3]), "r"(b0v), "r"(b1v))

// ---------------------------------------------------------------------------
// Kernel 0: merged prep. Blocks [0,4096): transpose NCHW fp32 -> NHWC fp16.
// Blocks [4096, 6400): weights fp16 with K permutation k' = kk*256 + c.
// ---------------------------------------------------------------------------
__global__ __launch_bounds__(256) void prep_kernel(
    const float* __restrict__ in, const float* __restrict__ w)
{
    if (blockIdx.x < 4096) {
        __shared__ float tile[32][33];
        const int bb  = blockIdx.x;
        const int hw0 = (bb & 127) * 32;
        const int c0  = ((bb >> 7) & 7) * 32;
        const int b   = bb >> 10;
        const int tx  = threadIdx.x & 31;
        const int ty  = threadIdx.x >> 5;

#pragma unroll
        for (int j = 0; j < 4; ++j) {
            const int c = c0 + ty + j * 8;
            tile[ty + j * 8][tx] = in[((size_t)(b * Cd + c)) * HW + hw0 + tx];
        }
        __syncthreads();
#pragma unroll
        for (int j = 0; j < 4; ++j) {
            const int hw = hw0 + ty + j * 8;
            g_inT[((size_t)(b * HW + hw)) * Cd + c0 + tx] = __float2half_rn(tile[tx][ty + j * 8]);
        }
    } else {
        const int i  = (blockIdx.x - 4096) * 256 + threadIdx.x;  // over 589824
        const int o  = i / KDIM;
        const int r  = i - o * KDIM;
        const int kk = r >> 8;
        const int c  = r & 255;
        g_w[i] = __float2half_rn(w[(o * Cd + c) * 9 + kk]);
    }
}

// ---------------------------------------------------------------------------
// Kernel 1: deformable bilinear sampling, NHWC (known good).
// ---------------------------------------------------------------------------
__global__ __launch_bounds__(256) void sample_kernel(
    const float* __restrict__ off, const float* __restrict__ mask)
{
    const int warp  = blockIdx.x * 8 + (threadIdx.x >> 5);
    const int lane  = threadIdx.x & 31;
    const int c0    = lane * 8;
    const int site0 = warp * 8;

#pragma unroll
    for (int it = 0; it < 8; ++it) {
        const int site = site0 + it;
        const int n  = site & (NTOT - 1);
        const int kk = site >> 14;
        const int b  = n >> 12;
        const int hw = n & 4095;
        const int h  = hw >> 6;
        const int w  = hw & 63;

        const float dy = off[((b * 18 + 2 * kk)     << 12) + hw];
        const float dx = off[((b * 18 + 2 * kk + 1) << 12) + hw];
        const float m  = mask[((b * 9 + kk)         << 12) + hw];

        const float y = (float)h + (float)(kk / 3 - 1) + dy;
        const float x = (float)w + (float)(kk % 3 - 1) + dx;
        const float y0f = floorf(y), x0f = floorf(x);
        const int   y0 = (int)y0f,  x0 = (int)x0f;
        const float wy1 = y - y0f, wx1 = x - x0f;
        const float wy0 = 1.0f - wy1, wx0 = 1.0f - wx1;

        const bool vy0 = (y0 >= 0) && (y0 < Hd);
        const bool vy1 = (y0 + 1 >= 0) && (y0 + 1 < Hd);
        const bool vx0 = (x0 >= 0) && (x0 < Wd);
        const bool vx1 = (x0 + 1 >= 0) && (x0 + 1 < Wd);

        const float w00 = (vy0 && vx0) ? wy0 * wx0 * m : 0.0f;
        const float w01 = (vy0 && vx1) ? wy0 * wx1 * m : 0.0f;
        const float w10 = (vy1 && vx0) ? wy1 * wx0 * m : 0.0f;
        const float w11 = (vy1 && vx1) ? wy1 * wx1 * m : 0.0f;

        const int i00 = (vy0 && vx0) ? (y0       * Wd + x0    ) : 0;
        const int i01 = (vy0 && vx1) ? (y0       * Wd + x0 + 1) : 0;
        const int i10 = (vy1 && vx0) ? ((y0 + 1) * Wd + x0    ) : 0;
        const int i11 = (vy1 && vx1) ? ((y0 + 1) * Wd + x0 + 1) : 0;

        const __half* base = g_inT + ((size_t)b * HW) * Cd + c0;
        union { uint4 u; __half2 h[4]; } u00, u01, u10, u11, res;
        u00.u = *(const uint4*)(base + (size_t)i00 * Cd);
        u01.u = *(const uint4*)(base + (size_t)i01 * Cd);
        u10.u = *(const uint4*)(base + (size_t)i10 * Cd);
        u11.u = *(const uint4*)(base + (size_t)i11 * Cd);

#pragma unroll
        for (int j = 0; j < 4; ++j) {
            const float2 f00 = __half22float2(u00.h[j]);
            const float2 f01 = __half22float2(u01.h[j]);
            const float2 f10 = __half22float2(u10.h[j]);
            const float2 f11 = __half22float2(u11.h[j]);
            const float rx = w00 * f00.x + w01 * f01.x + w10 * f10.x + w11 * f11.x;
            const float ry = w00 * f00.y + w01 * f01.y + w10 * f10.y + w11 * f11.y;
            res.h[j] = __floats2half2_rn(rx, ry);
        }
        *(uint4*)(g_cols + (size_t)n * KDIM + kk * 256 + c0) = res.u;
    }
}

// ---------------------------------------------------------------------------
// Stage loader: cp.async one BK=64 stage (A 1024 + B 1024 chunks), 8/thread
// ---------------------------------------------------------------------------
__device__ __forceinline__ void load_stage(uint32_t sbuf, int s, int m0, int n0, int tid)
{
    const int k0 = s * BK;
#pragma unroll
    for (int j = 0; j < 8; ++j) {
        const int c = tid + j * 256;
        if (c < 1024) {               // A: 128 rows x 8 chunks
            const int row = c >> 3, seg = c & 7;
            const __half* src = g_w + (m0 + row) * KDIM + k0 + seg * 8;
            CP_ASYNC(sbuf + A_OFF + row * A_ROW_B + seg * 16, src);
        } else {                      // B: 128 n-rows x 8 chunks
            const int cc  = c - 1024;
            const int row = cc >> 3, seg = cc & 7;
            const __half* src = g_cols + (size_t)(n0 + row) * KDIM + k0 + seg * 8;
            CP_ASYNC(sbuf + B_OFF + row * B_ROW_B + seg * 16, src);
        }
    }
    CP_COMMIT();
}

// ---------------------------------------------------------------------------
// Kernel 2: fp16 GEMM via mma.sync + fused GN partial stats.
// grid (2 m-tiles, 128 n-tiles), 256 threads, warp tile 64x32, 2 CTA/SM.
// BK=64: 4 kkp per stage between barriers, 36 stages, double-buffered.
// ---------------------------------------------------------------------------
__global__ __launch_bounds__(256, 2) void gemm_mma(
    const float* __restrict__ bias, float* __restrict__ out)
{
    extern __shared__ char smem[];
    const uint32_t sb = smem_u32(smem);
    const int tid = threadIdx.x;
    const int wid = tid >> 5;
    const int lid = tid & 31;
    const int wm  = wid >> 2;        // 0..1 -> 64-row warp tile
    const int wn  = wid & 3;         // 0..3 -> 32-col warp tile
    const int m0  = blockIdx.x * BM;
    const int n0  = blockIdx.y * BN;

    float acc[4][4][4];
#pragma unroll
    for (int i = 0; i < 4; ++i)
#pragma unroll
        for (int j = 0; j < 4; ++j)
#pragma unroll
            for (int r = 0; r < 4; ++r) acc[i][j][r] = 0.0f;

    load_stage(sb, 0, m0, n0, tid);

    const uint32_t a_lane = (uint32_t)((lid & 15) * A_ROW_B + (lid >> 4) * 16);
    const uint32_t b_lane = (uint32_t)((((lid >> 4) << 3) + (lid & 7)) * B_ROW_B
                                       + ((lid >> 3) & 1) * 16);

    for (int s = 0; s < NSTG; ++s) {
        CP_WAIT(0);                    // stage s arrived
        __syncthreads();               // everyone done with buffer (s+1)&1
        if (s + 1 < NSTG)
            load_stage(sb + (uint32_t)((s + 1) & 1) * STAGE_B, s + 1, m0, n0, tid);

        const uint32_t sbuf = sb + (uint32_t)(s & 1) * STAGE_B;

#pragma unroll
        for (int kkp = 0; kkp < 4; ++kkp) {
            uint32_t af[4][4];
#pragma unroll
            for (int i = 0; i < 4; ++i) {
                const uint32_t addr = sbuf + A_OFF + (uint32_t)((wm * 64 + i * 16) * A_ROW_B)
                                    + (uint32_t)(kkp * 32) + a_lane;
                LDMATRIX_X4(af[i][0], af[i][1], af[i][2], af[i][3], addr);
            }
            uint32_t bf[2][4];
#pragma unroll
            for (int j2 = 0; j2 < 2; ++j2) {
                const uint32_t addr = sbuf + B_OFF + (uint32_t)((wn * 32 + j2 * 16) * B_ROW_B)
                                    + (uint32_t)(kkp * 32) + b_lane;
                LDMATRIX_X4(bf[j2][0], bf[j2][1], bf[j2][2], bf[j2][3], addr);
            }
#pragma unroll
            for (int i = 0; i < 4; ++i)
#pragma unroll
                for (int j = 0; j < 4; ++j)
                    MMA_F16(acc[i][j], af[i], bf[j >> 1][(j & 1) * 2], bf[j >> 1][(j & 1) * 2 + 1]);
        }
    }

    // epilogue: write out + per-group warp-reduced partial stats.
    const int b   = n0 >> 12;
    const int hwb = n0 & 4095;
    const int slot = ((blockIdx.y & 31) << 2) + wn;   // 0..127
#pragma unroll
    for (int i = 0; i < 4; ++i) {
        const int o_lo = m0 + wm * 64 + i * 16 + (lid >> 2);
        const float bi0 = bias[o_lo];
        const float bi1 = bias[o_lo + 8];
        float s = 0.0f, q = 0.0f;
#pragma unroll
        for (int j = 0; j < 4; ++j) {
            const int nc = hwb + wn * 32 + j * 8 + (lid & 3) * 2;
            float v0x = acc[i][j][0] + bi0, v0y = acc[i][j][1] + bi0;
            float v1x = acc[i][j][2] + bi1, v1y = acc[i][j][3] + bi1;
            s += v0x + v0y + v1x + v1y;
            q += v0x * v0x + v0y * v0y + v1x * v1x + v1y * v1y;
            *(float2*)(out + (((size_t)(b * COd + o_lo))     << 12) + nc) = make_float2(v0x, v0y);
            *(float2*)(out + (((size_t)(b * COd + o_lo + 8)) << 12) + nc) = make_float2(v1x, v1y);
        }
#pragma unroll
        for (int d = 16; d > 0; d >>= 1) {
            s += __shfl_xor_sync(0xFFFFFFFFu, s, d);
            q += __shfl_xor_sync(0xFFFFFFFFu, q, d);
        }
        if (lid == 0) {
            const int g = (m0 >> 4) + wm * 4 + i;      // 0..15
            g_part2[(b * 16 + g) * 128 + slot] = make_float2(s, q);
        }
    }
}

// ---------------------------------------------------------------------------
// Kernel 3: finalize stats — 64 blocks x 128 thr, one (b,g) per block.
// ---------------------------------------------------------------------------
__global__ __launch_bounds__(128) void finalize_kernel()
{
    __shared__ float sh_s[128], sh_q[128];
    const int bg = blockIdx.x;
    float2 p = g_part2[bg * 128 + threadIdx.x];
    sh_s[threadIdx.x] = p.x;
    sh_q[threadIdx.x] = p.y;
    __syncthreads();
    for (int st = 64; st > 0; st >>= 1) {
        if (threadIdx.x < st) {
            sh_s[threadIdx.x] += sh_s[threadIdx.x + st];
            sh_q[threadIdx.x] += sh_q[threadIdx.x + st];
        }
        __syncthreads();
    }
    if (threadIdx.x == 0) {
        const float cnt = 65536.0f;
        const float mu  = sh_s[0] / cnt;
        const float var = sh_q[0] / cnt - mu * mu;
        g_mufin[bg] = make_float2(mu, rsqrtf(var + 1e-5f));
    }
}

// ---------------------------------------------------------------------------
// Kernel 4: normalize in place (reads finalized stats)
// ---------------------------------------------------------------------------
__global__ __launch_bounds__(256) void norm_kernel(
    float* __restrict__ out, const float* __restrict__ gamma,
    const float* __restrict__ beta)
{
    const int fi0 = blockIdx.x << 10;     // 1024 floats per block
    const int o   = (fi0 >> 12) & 255;
    const int b   = fi0 >> 20;
    const int bg  = b * 16 + (o >> 4);

    const float2 mf = g_mufin[bg];
    const float ga  = gamma[o] * mf.y;
    const float be  = beta[o] - mf.x * ga;

    const int idx = (fi0 >> 2) + threadIdx.x;
    float4 v = ((const float4*)out)[idx];
    v.x = v.x * ga + be; v.y = v.y * ga + be;
    v.z = v.z * ga + be; v.w = v.w * ga + be;
    ((float4*)out)[idx] = v;
}

// ---------------------------------------------------------------------------
extern "C" void kernel_launch(void* const* d_in, const int* in_sizes, int n_in,
                              void* d_out, int out_size)
{
    const float* input  = (const float*)d_in[0];
    const float* offset = (const float*)d_in[1];
    const float* mask   = (const float*)d_in[2];
    const float* weight = (const float*)d_in[3];
    const float* bias   = (const float*)d_in[4];
    const float* gamma  = (const float*)d_in[5];
    const float* beta   = (const float*)d_in[6];
    float* out = (float*)d_out;

    cudaFuncSetAttribute(gemm_mma, cudaFuncAttributeMaxDynamicSharedMemorySize, SMEM_TOTAL);

    prep_kernel<<<4096 + COd * KDIM / 256, 256>>>(input, weight);

    sample_kernel<<<2304, 256>>>(offset, mask);

    dim3 gg(COd / BM, NTOT / BN);
    gemm_mma<<<gg, 256, SMEM_TOTAL>>>(bias, out);

    finalize_kernel<<<64, 128>>>();

    norm_kernel<<<Bd * COd * HW / 1024, 256>>>(out, gamma, beta);
}